// round 10
// baseline (speedup 1.0000x reference)
#include <cuda_runtime.h>
#include <math.h>
#include <cstdint>

#define B_CONST 2
#define H_NUM   16
#define HD      32
#define NSPLIT  2

typedef unsigned long long u64;

// ---------------- device scratch ----------------
__device__ float g_q [2*2048*512];
__device__ float g_k [2*2048*512];
__device__ float g_v [2*2048*512];
__device__ float g_ao[2*2048*512];
__device__ float g_pacc[NSPLIT * 2*2048*16 * 32];
__device__ float g_pm  [NSPLIT * 2*2048*16];
__device__ float g_pl  [NSPLIT * 2*2048*16];
__device__ int g_gcols[64];
__device__ int g_gcount;

// ---------------- packed f32x2 helpers ----------------
__device__ __forceinline__ u64 pack2(float lo, float hi) {
    u64 r; asm("mov.b64 %0, {%1, %2};" : "=l"(r) : "f"(lo), "f"(hi)); return r;
}
__device__ __forceinline__ void unpack2(u64 v, float& lo, float& hi) {
    asm("mov.b64 {%0, %1}, %2;" : "=f"(lo), "=f"(hi) : "l"(v));
}
__device__ __forceinline__ u64 fma2(u64 a, u64 b, u64 c) {
    u64 d; asm("fma.rn.f32x2 %0, %1, %2, %3;" : "=l"(d) : "l"(a), "l"(b), "l"(c)); return d;
}
__device__ __forceinline__ u64 mul2(u64 a, u64 b) {
    u64 d; asm("mul.rn.f32x2 %0, %1, %2;" : "=l"(d) : "l"(a), "l"(b)); return d;
}
__device__ __forceinline__ u64 add2(u64 a, u64 b) {
    u64 d; asm("add.rn.f32x2 %0, %1, %2;" : "=l"(d) : "l"(a), "l"(b)); return d;
}

// ---------------- global-token column list ----------------
__global__ void glist_kernel(int S, const int* __restrict__ Gptr) {
    if (threadIdx.x != 0 || blockIdx.x != 0) return;
    int G = *Gptr;
    int n = 0;
    if (G > 0) {
        int stride = S / (G + 1);
        if (G == 1) {
            g_gcols[n++] = stride;
        } else {
            double stp = (double)(S - 2 * stride) / (double)(G - 1);
            for (int t = 0; t < G && n < 64; t++) {
                long long gi = (t == G - 1)
                    ? (long long)(S - stride)
                    : (long long)((double)t * stp + (double)stride);
                bool dup = false;
                for (int u = 0; u < n; u++) if (g_gcols[u] == (int)gi) dup = true;
                if (!dup) g_gcols[n++] = (int)gi;
            }
        }
    }
    g_gcount = n;
}

// ---------------- TF32 mma.sync GEMM: C = (A@W^T + b) * alpha ---------------
#define BMG 128
#define BNG 128
#define BKG 32
#define SSTR 36
#define GEMM_SMEM (2 * (BMG + BNG) * SSTR * 4)   // 73728 bytes

__device__ __forceinline__ uint32_t f2tf32(float x) {
    uint32_t r;
    asm("cvt.rna.tf32.f32 %0, %1;" : "=r"(r) : "f"(x));
    return r;
}

__device__ __forceinline__ void mma_tf32(float* c, const uint32_t* a, const uint32_t* b) {
    asm volatile(
        "mma.sync.aligned.m16n8k8.row.col.f32.tf32.tf32.f32 "
        "{%0,%1,%2,%3}, {%4,%5,%6,%7}, {%8,%9}, {%0,%1,%2,%3};"
        : "+f"(c[0]), "+f"(c[1]), "+f"(c[2]), "+f"(c[3])
        : "r"(a[0]), "r"(a[1]), "r"(a[2]), "r"(a[3]), "r"(b[0]), "r"(b[1]));
}

__device__ void gemm_core(const float* __restrict__ A, const float* __restrict__ W,
                          const float* __restrict__ bias, float* __restrict__ C,
                          int M, int N, int K, float alpha, float* sm) {
    float* As = sm;
    float* Bs = sm + 2 * BMG * SSTR;

    int tid = threadIdx.x;
    int warp = tid >> 5, lane = tid & 31;
    int warp_m = warp >> 2;
    int warp_n = warp & 3;
    int gr = lane >> 2, gc = lane & 3;

    int bm = blockIdx.y * BMG;
    int bn = blockIdx.x * BNG;

    int lrow = tid >> 3;
    int lc4  = (tid & 7) * 4;

    const float* Ap = A + (size_t)(bm + lrow) * K + lc4;
    const float* Wp = W + (size_t)(bn + lrow) * K + lc4;

    float c[4][4][4];
#pragma unroll
    for (int t = 0; t < 4; t++)
#pragma unroll
        for (int u = 0; u < 4; u++)
#pragma unroll
            for (int e = 0; e < 4; e++) c[t][u][e] = 0.f;

    float4 areg[4], breg[4];
    int nch = K / BKG;

#pragma unroll
    for (int it = 0; it < 4; it++) {
        areg[it] = *(const float4*)(Ap + (size_t)it * 32 * K);
        breg[it] = *(const float4*)(Wp + (size_t)it * 32 * K);
    }
#pragma unroll
    for (int it = 0; it < 4; it++) {
        float* da = As + (lrow + it * 32) * SSTR + lc4;
        float* db = Bs + (lrow + it * 32) * SSTR + lc4;
        ((uint32_t*)da)[0] = f2tf32(areg[it].x); ((uint32_t*)da)[1] = f2tf32(areg[it].y);
        ((uint32_t*)da)[2] = f2tf32(areg[it].z); ((uint32_t*)da)[3] = f2tf32(areg[it].w);
        ((uint32_t*)db)[0] = f2tf32(breg[it].x); ((uint32_t*)db)[1] = f2tf32(breg[it].y);
        ((uint32_t*)db)[2] = f2tf32(breg[it].z); ((uint32_t*)db)[3] = f2tf32(breg[it].w);
    }
    __syncthreads();

    for (int ch = 0; ch < nch; ch++) {
        int buf = ch & 1;
        if (ch + 1 < nch) {
            int k0n = (ch + 1) * BKG;
#pragma unroll
            for (int it = 0; it < 4; it++) {
                areg[it] = *(const float4*)(Ap + (size_t)it * 32 * K + k0n);
                breg[it] = *(const float4*)(Wp + (size_t)it * 32 * K + k0n);
            }
        }
        const uint32_t* as = (const uint32_t*)(As + buf * BMG * SSTR + warp_m * 64 * SSTR);
        const uint32_t* bs = (const uint32_t*)(Bs + buf * BNG * SSTR + warp_n * 32 * SSTR);
#pragma unroll
        for (int ks = 0; ks < 4; ks++) {
            int k0 = ks * 8;
            uint32_t af[4][4], bf[4][2];
#pragma unroll
            for (int t = 0; t < 4; t++) {
                int row = t * 16 + gr;
                af[t][0] = as[row * SSTR + k0 + gc];
                af[t][1] = as[(row + 8) * SSTR + k0 + gc];
                af[t][2] = as[row * SSTR + k0 + gc + 4];
                af[t][3] = as[(row + 8) * SSTR + k0 + gc + 4];
            }
#pragma unroll
            for (int u = 0; u < 4; u++) {
                int col = u * 8 + gr;
                bf[u][0] = bs[col * SSTR + k0 + gc];
                bf[u][1] = bs[col * SSTR + k0 + gc + 4];
            }
#pragma unroll
            for (int t = 0; t < 4; t++)
#pragma unroll
                for (int u = 0; u < 4; u++)
                    mma_tf32(c[t][u], af[t], bf[u]);
        }
        __syncthreads();
        if (ch + 1 < nch) {
            int nbuf = (ch + 1) & 1;
#pragma unroll
            for (int it = 0; it < 4; it++) {
                float* da = As + nbuf * BMG * SSTR + (lrow + it * 32) * SSTR + lc4;
                float* db = Bs + nbuf * BNG * SSTR + (lrow + it * 32) * SSTR + lc4;
                ((uint32_t*)da)[0] = f2tf32(areg[it].x); ((uint32_t*)da)[1] = f2tf32(areg[it].y);
                ((uint32_t*)da)[2] = f2tf32(areg[it].z); ((uint32_t*)da)[3] = f2tf32(areg[it].w);
                ((uint32_t*)db)[0] = f2tf32(breg[it].x); ((uint32_t*)db)[1] = f2tf32(breg[it].y);
                ((uint32_t*)db)[2] = f2tf32(breg[it].z); ((uint32_t*)db)[3] = f2tf32(breg[it].w);
            }
            __syncthreads();
        }
    }

#pragma unroll
    for (int t = 0; t < 4; t++) {
        int row = bm + warp_m * 64 + t * 16 + gr;
#pragma unroll
        for (int u = 0; u < 4; u++) {
            int col = bn + warp_n * 32 + u * 8 + 2 * gc;
            float2 bb = *(const float2*)(bias + col);
            float2 o0, o1;
            o0.x = (c[t][u][0] + bb.x) * alpha;
            o0.y = (c[t][u][1] + bb.y) * alpha;
            o1.x = (c[t][u][2] + bb.x) * alpha;
            o1.y = (c[t][u][3] + bb.y) * alpha;
            *(float2*)(C + (size_t)row * N + col) = o0;
            *(float2*)(C + (size_t)(row + 8) * N + col) = o1;
        }
    }
}

__global__ __launch_bounds__(256)
void qkv_gemm_kernel(const float* q_in, const float* k_in, const float* v_in,
                     const float* Wq, const float* Wk, const float* Wv,
                     const float* bq, const float* bk, const float* bv,
                     float* qo, float* ko, float* vo,
                     int M, int N, int K, float scaling,
                     const float* __restrict__ temp_ptr) {
    extern __shared__ float smg[];
    int z = blockIdx.z;
    const float* A; const float* W; const float* bias; float* C; float alpha;
    if (z == 0)      { A = q_in; W = Wq; bias = bq; C = qo; alpha = scaling * (*temp_ptr); }
    else if (z == 1) { A = k_in; W = Wk; bias = bk; C = ko; alpha = 1.0f; }
    else             { A = v_in; W = Wv; bias = bv; C = vo; alpha = 1.0f; }
    gemm_core(A, W, bias, C, M, N, K, alpha, smg);
}

__global__ __launch_bounds__(256)
void oproj_gemm_kernel(const float* __restrict__ A, const float* __restrict__ W,
                       const float* __restrict__ bias, float* __restrict__ C,
                       int M, int N, int K) {
    extern __shared__ float smg[];
    gemm_core(A, W, bias, C, M, N, K, 1.0f, smg);
}

// ---------------- sparse flash attention v8: split-KV x2 -------------------
// blockIdx.x = tilex*2 + split. Split s processes column tiles with parity s
// (disjoint, union = all tiles; no duplicated K/V loads). Split 0 also does
// the global-column gather pass. Partials (m, l, unnormalized acc) go to
// g_pm/g_pl/g_pacc; merge_kernel combines.
#define AT_BM 128
#define AT_BN 64
#define KS_STR 36
#define ATT_SMEM (2 * AT_BN * KS_STR * 4 + 64)

__global__ __launch_bounds__(128)
void sparse_attn_kernel(int T, int S, int E, int nrows, const int* __restrict__ Wptr) {
    extern __shared__ float sm[];
    float* Ks = sm;                      // [AT_BN][KS_STR]
    float* Vs = sm + AT_BN * KS_STR;     // [AT_BN][KS_STR]

    int b = blockIdx.z, h = blockIdx.y;
    int split = blockIdx.x & 1;
    int i0 = (blockIdx.x >> 1) * AT_BM;
    int t = threadIdx.x;
    int i = i0 + t;

    const float* qrow = g_q + ((size_t)(b * T + i)) * E + h * HD;
    u64 q2[16];
#pragma unroll
    for (int d8 = 0; d8 < 8; d8++) {
        ulonglong2 v = *(const ulonglong2*)(qrow + d8 * 4);
        q2[d8 * 2] = v.x; q2[d8 * 2 + 1] = v.y;
    }

    float mrow = -INFINITY, l = 0.f;
    u64 acc2[16];
#pragma unroll
    for (int d = 0; d < 16; d++) acc2[d] = 0ull;

    int Wl = *Wptr;
    int ov = Wl / 4, step = Wl - ov;

    int klo = (i >= Wl) ? (i - Wl) / step + 1 : 0;
    int khi = i / step;
    int rlo = max(0, klo * step - ov);
    int rhi = min(S, khi * step + Wl + ov);

    int cklo = (i0 >= Wl) ? (i0 - Wl) / step + 1 : 0;
    int ckhi = (i0 + AT_BM - 1) / step;
    int c_lo = max(0, cklo * step - ov);
    int c_hi = min(S, ckhi * step + Wl + ov);

    const float* kbase = g_k + (size_t)b * S * E + h * HD;
    const float* vbase = g_v + (size_t)b * S * E + h * HD;

    int ldrow = t >> 1, ldhalf = (t & 1) * 16;

    int jstart = (c_lo & ~(AT_BN - 1)) + split * AT_BN;
    for (int j0 = jstart; j0 < c_hi; j0 += 2 * AT_BN) {
        {
            const float* kp = kbase + (size_t)(j0 + ldrow) * E + ldhalf;
            const float* vp = vbase + (size_t)(j0 + ldrow) * E + ldhalf;
#pragma unroll
            for (int c = 0; c < 16; c += 4) {
                *(float4*)&Ks[ldrow * KS_STR + ldhalf + c] = *(const float4*)(kp + c);
                *(float4*)&Vs[ldrow * KS_STR + ldhalf + c] = *(const float4*)(vp + c);
            }
        }
        __syncthreads();

        int jlo = max(rlo, j0) - j0;
        int jhi = min(rhi, j0 + AT_BN) - j0;

        for (int jc = jlo; jc < jhi; jc += 8) {
            float s[8];
            float cmax = -INFINITY;
#pragma unroll
            for (int c = 0; c < 8; c++) {
                s[c] = -INFINITY;
                if (jc + c < jhi) {
                    const ulonglong2* kr = (const ulonglong2*)&Ks[(jc + c) * KS_STR];
                    u64 z0 = 0ull, z1 = 0ull, z2 = 0ull, z3 = 0ull;
#pragma unroll
                    for (int d4 = 0; d4 < 4; d4++) {
                        ulonglong2 k0 = kr[d4 * 2];
                        ulonglong2 k1 = kr[d4 * 2 + 1];
                        z0 = fma2(q2[d4 * 4 + 0], k0.x, z0);
                        z1 = fma2(q2[d4 * 4 + 1], k0.y, z1);
                        z2 = fma2(q2[d4 * 4 + 2], k1.x, z2);
                        z3 = fma2(q2[d4 * 4 + 3], k1.y, z3);
                    }
                    u64 zz = add2(add2(z0, z2), add2(z1, z3));
                    float a0, a1;
                    unpack2(zz, a0, a1);
                    s[c] = a0 + a1;
                    cmax = fmaxf(cmax, s[c]);
                }
            }
            if (cmax > -INFINITY) {
                float mnew = fmaxf(mrow, cmax);
                if (mnew > mrow) {
                    if (mrow > -INFINITY) {
                        float cs = __expf(mrow - mnew);
                        l *= cs;
                        u64 cs2 = pack2(cs, cs);
#pragma unroll
                        for (int d = 0; d < 16; d++) acc2[d] = mul2(acc2[d], cs2);
                    }
                    mrow = mnew;
                }
#pragma unroll
                for (int c = 0; c < 8; c++) {
                    float p = __expf(s[c] - mrow);       // -inf lanes -> 0
                    l += p;
                    int jv = min(jc + c, AT_BN - 1);     // clamp; p=0 there
                    u64 pp = pack2(p, p);
                    const ulonglong2* vr = (const ulonglong2*)&Vs[jv * KS_STR];
#pragma unroll
                    for (int d8 = 0; d8 < 8; d8++) {
                        ulonglong2 vv = vr[d8];
                        acc2[d8 * 2]     = fma2(pp, vv.x, acc2[d8 * 2]);
                        acc2[d8 * 2 + 1] = fma2(pp, vv.y, acc2[d8 * 2 + 1]);
                    }
                }
            }
        }
        __syncthreads();
    }

    // gather pass (split 0 only): globals outside this row's [rlo, rhi)
    int ng = (split == 0) ? g_gcount : 0;
    if (ng > 0) {
        for (int idx = t; idx < ng * 2; idx += AT_BM) {
            int row = idx >> 1, half = (idx & 1) * 16;
            int j = g_gcols[row];
            const float* kp = kbase + (size_t)j * E + half;
            const float* vp = vbase + (size_t)j * E + half;
#pragma unroll
            for (int c = 0; c < 16; c += 4) {
                *(float4*)&Ks[row * KS_STR + half + c] = *(const float4*)(kp + c);
                *(float4*)&Vs[row * KS_STR + half + c] = *(const float4*)(vp + c);
            }
        }
        __syncthreads();

        for (int jc = 0; jc < ng; jc += 8) {
            float s[8];
            float cmax = -INFINITY;
#pragma unroll
            for (int c = 0; c < 8; c++) {
                s[c] = -INFINITY;
                if (jc + c < ng) {
                    int j = g_gcols[jc + c];
                    if (j < rlo || j >= rhi) {
                        const ulonglong2* kr = (const ulonglong2*)&Ks[(jc + c) * KS_STR];
                        u64 z0 = 0ull, z1 = 0ull, z2 = 0ull, z3 = 0ull;
#pragma unroll
                        for (int d4 = 0; d4 < 4; d4++) {
                            ulonglong2 k0 = kr[d4 * 2];
                            ulonglong2 k1 = kr[d4 * 2 + 1];
                            z0 = fma2(q2[d4 * 4 + 0], k0.x, z0);
                            z1 = fma2(q2[d4 * 4 + 1], k0.y, z1);
                            z2 = fma2(q2[d4 * 4 + 2], k1.x, z2);
                            z3 = fma2(q2[d4 * 4 + 3], k1.y, z3);
                        }
                        u64 zz = add2(add2(z0, z2), add2(z1, z3));
                        float a0, a1;
                        unpack2(zz, a0, a1);
                        s[c] = a0 + a1;
                        cmax = fmaxf(cmax, s[c]);
                    }
                }
            }
            if (cmax > -INFINITY) {
                float mnew = fmaxf(mrow, cmax);
                if (mnew > mrow) {
                    if (mrow > -INFINITY) {
                        float cs = __expf(mrow - mnew);
                        l *= cs;
                        u64 cs2 = pack2(cs, cs);
#pragma unroll
                        for (int d = 0; d < 16; d++) acc2[d] = mul2(acc2[d], cs2);
                    }
                    mrow = mnew;
                }
#pragma unroll
                for (int c = 0; c < 8; c++) {
                    float p = __expf(s[c] - mrow);
                    l += p;
                    int jv = min(jc + c, AT_BN - 1);
                    u64 pp = pack2(p, p);
                    const ulonglong2* vr = (const ulonglong2*)&Vs[jv * KS_STR];
#pragma unroll
                    for (int d8 = 0; d8 < 8; d8++) {
                        ulonglong2 vv = vr[d8];
                        acc2[d8 * 2]     = fma2(pp, vv.x, acc2[d8 * 2]);
                        acc2[d8 * 2 + 1] = fma2(pp, vv.y, acc2[d8 * 2 + 1]);
                    }
                }
            }
        }
    }

    // write partials (unnormalized)
    int r = (b * T + i) * H_NUM + h;
    size_t pidx = (size_t)split * nrows + r;
    g_pm[pidx] = mrow;
    g_pl[pidx] = l;
    float* pa = &g_pacc[pidx * 32];
#pragma unroll
    for (int d8 = 0; d8 < 8; d8++) {
        float x0, x1, x2, x3;
        unpack2(acc2[d8 * 2],     x0, x1);
        unpack2(acc2[d8 * 2 + 1], x2, x3);
        float4 o; o.x = x0; o.y = x1; o.z = x2; o.w = x3;
        *(float4*)(pa + d8 * 4) = o;
    }
}

// merge partials -> g_ao
__global__ void merge_kernel(int T, int E, int nrows) {
    int r = blockIdx.x * blockDim.x + threadIdx.x;
    if (r >= nrows) return;
    float m0 = g_pm[r], m1 = g_pm[(size_t)nrows + r];
    float l0 = g_pl[r], l1 = g_pl[(size_t)nrows + r];
    float m = fmaxf(m0, m1);
    float w0 = (m0 == -INFINITY) ? 0.f : __expf(m0 - m);
    float w1 = (m1 == -INFINITY) ? 0.f : __expf(m1 - m);
    float inv = 1.0f / (l0 * w0 + l1 * w1);
    const float4* a0 = (const float4*)&g_pacc[(size_t)r * 32];
    const float4* a1 = (const float4*)&g_pacc[((size_t)nrows + r) * 32];
    int h = r % H_NUM;
    int bi = r / H_NUM;
    float* orow = g_ao + (size_t)bi * E + h * HD;
#pragma unroll
    for (int d = 0; d < 8; d++) {
        float4 x0 = a0[d], x1 = a1[d];
        float4 o;
        o.x = (x0.x * w0 + x1.x * w1) * inv;
        o.y = (x0.y * w0 + x1.y * w1) * inv;
        o.z = (x0.z * w0 + x1.z * w1) * inv;
        o.w = (x0.w * w0 + x1.w * w1) * inv;
        *(float4*)(orow + d * 4) = o;
    }
}

// ---------------- launch -----------------------------------------------------
extern "C" void kernel_launch(void* const* d_in, const int* in_sizes, int n_in,
                              void* d_out, int out_size) {
    const float* query = (const float*)d_in[0];
    const float* key_  = (const float*)d_in[1];
    const float* value = (const float*)d_in[2];
    const float* Wq = (const float*)d_in[3];
    const float* bq = (const float*)d_in[4];
    const float* Wk = (const float*)d_in[5];
    const float* bk = (const float*)d_in[6];
    const float* Wv = (const float*)d_in[7];
    const float* bv = (const float*)d_in[8];
    const float* Wo = (const float*)d_in[9];
    const float* bo = (const float*)d_in[10];
    const float* temperature = (const float*)d_in[11];
    const int* wsize = (const int*)d_in[12];
    const int* gnum  = (const int*)d_in[13];
    float* out = (float*)d_out;

    int E = in_sizes[4];                 // 512
    int B = B_CONST;
    int T = in_sizes[0] / (B * E);       // 2048
    int S = in_sizes[1] / (B * E);       // 2048
    int M = B * T;                       // 4096
    int hd = E / H_NUM;
    int nrows = B * T * H_NUM;           // 65536

    float *qb, *kb, *vb, *aob;
    cudaGetSymbolAddress((void**)&qb,  g_q);
    cudaGetSymbolAddress((void**)&kb,  g_k);
    cudaGetSymbolAddress((void**)&vb,  g_v);
    cudaGetSymbolAddress((void**)&aob, g_ao);

    glist_kernel<<<1, 32>>>(S, gnum);

    cudaFuncSetAttribute(qkv_gemm_kernel,
                         cudaFuncAttributeMaxDynamicSharedMemorySize, GEMM_SMEM);
    cudaFuncSetAttribute(oproj_gemm_kernel,
                         cudaFuncAttributeMaxDynamicSharedMemorySize, GEMM_SMEM);

    float scaling = 1.0f / sqrtf((float)hd);
    dim3 qkv_grid(E / BNG, M / BMG, 3);          // (4, 32, 3)
    qkv_gemm_kernel<<<qkv_grid, 256, GEMM_SMEM>>>(
        query, key_, value, Wq, Wk, Wv, bq, bk, bv,
        qb, kb, vb, M, E, E, scaling, temperature);

    cudaFuncSetAttribute(sparse_attn_kernel,
                         cudaFuncAttributeMaxDynamicSharedMemorySize, ATT_SMEM);
    sparse_attn_kernel<<<dim3((T / AT_BM) * NSPLIT, H_NUM, B), AT_BM, ATT_SMEM>>>(
        T, S, E, nrows, wsize);

    merge_kernel<<<(nrows + 255) / 256, 256>>>(T, E, nrows);

    dim3 ogrid(E / BNG, M / BMG);                // (4, 32)
    oproj_gemm_kernel<<<ogrid, 256, GEMM_SMEM>>>(aob, Wo, bo, out, M, E, E);
}

// round 11
// speedup vs baseline: 1.3275x; 1.3275x over previous
#include <cuda_runtime.h>
#include <math.h>
#include <cstdint>

#define B_CONST 2
#define H_NUM   16
#define HD      32

// ---------------- device scratch ----------------
__device__ float g_q [2*2048*512];
__device__ float g_k [2*2048*512];
__device__ float g_v [2*2048*512];
__device__ float g_ao[2*2048*512];
__device__ int g_gcols[64];
__device__ int g_gcount;

// ---------------- global-token column list ----------------
__global__ void glist_kernel(int S, const int* __restrict__ Gptr) {
    if (threadIdx.x != 0 || blockIdx.x != 0) return;
    int G = *Gptr;
    int n = 0;
    if (G > 0) {
        int stride = S / (G + 1);
        if (G == 1) {
            g_gcols[n++] = stride;
        } else {
            double stp = (double)(S - 2 * stride) / (double)(G - 1);
            for (int t = 0; t < G && n < 64; t++) {
                long long gi = (t == G - 1)
                    ? (long long)(S - stride)
                    : (long long)((double)t * stp + (double)stride);
                bool dup = false;
                for (int u = 0; u < n; u++) if (g_gcols[u] == (int)gi) dup = true;
                if (!dup) g_gcols[n++] = (int)gi;
            }
        }
    }
    g_gcount = n;
}

// ---------------- shared helpers ----------------
__device__ __forceinline__ uint32_t f2tf32(float x) {
    uint32_t r;
    asm("cvt.rna.tf32.f32 %0, %1;" : "=r"(r) : "f"(x));
    return r;
}

__device__ __forceinline__ void mma_tf32(float* c, const uint32_t* a, const uint32_t* b) {
    asm volatile(
        "mma.sync.aligned.m16n8k8.row.col.f32.tf32.tf32.f32 "
        "{%0,%1,%2,%3}, {%4,%5,%6,%7}, {%8,%9}, {%0,%1,%2,%3};"
        : "+f"(c[0]), "+f"(c[1]), "+f"(c[2]), "+f"(c[3])
        : "r"(a[0]), "r"(a[1]), "r"(a[2]), "r"(a[3]), "r"(b[0]), "r"(b[1]));
}

// ---------------- TF32 mma.sync GEMM: C = (A@W^T + b) * alpha ---------------
#define BMG 128
#define BNG 128
#define BKG 32
#define SSTR 36
#define GEMM_SMEM (2 * (BMG + BNG) * SSTR * 4)   // 73728 bytes

__device__ void gemm_core(const float* __restrict__ A, const float* __restrict__ W,
                          const float* __restrict__ bias, float* __restrict__ C,
                          int M, int N, int K, float alpha, float* sm) {
    float* As = sm;
    float* Bs = sm + 2 * BMG * SSTR;

    int tid = threadIdx.x;
    int warp = tid >> 5, lane = tid & 31;
    int warp_m = warp >> 2;
    int warp_n = warp & 3;
    int gr = lane >> 2, gc = lane & 3;

    int bm = blockIdx.y * BMG;
    int bn = blockIdx.x * BNG;

    int lrow = tid >> 3;
    int lc4  = (tid & 7) * 4;

    const float* Ap = A + (size_t)(bm + lrow) * K + lc4;
    const float* Wp = W + (size_t)(bn + lrow) * K + lc4;

    float c[4][4][4];
#pragma unroll
    for (int t = 0; t < 4; t++)
#pragma unroll
        for (int u = 0; u < 4; u++)
#pragma unroll
            for (int e = 0; e < 4; e++) c[t][u][e] = 0.f;

    float4 areg[4], breg[4];
    int nch = K / BKG;

#pragma unroll
    for (int it = 0; it < 4; it++) {
        areg[it] = *(const float4*)(Ap + (size_t)it * 32 * K);
        breg[it] = *(const float4*)(Wp + (size_t)it * 32 * K);
    }
#pragma unroll
    for (int it = 0; it < 4; it++) {
        float* da = As + (lrow + it * 32) * SSTR + lc4;
        float* db = Bs + (lrow + it * 32) * SSTR + lc4;
        ((uint32_t*)da)[0] = f2tf32(areg[it].x); ((uint32_t*)da)[1] = f2tf32(areg[it].y);
        ((uint32_t*)da)[2] = f2tf32(areg[it].z); ((uint32_t*)da)[3] = f2tf32(areg[it].w);
        ((uint32_t*)db)[0] = f2tf32(breg[it].x); ((uint32_t*)db)[1] = f2tf32(breg[it].y);
        ((uint32_t*)db)[2] = f2tf32(breg[it].z); ((uint32_t*)db)[3] = f2tf32(breg[it].w);
    }
    __syncthreads();

    for (int ch = 0; ch < nch; ch++) {
        int buf = ch & 1;
        if (ch + 1 < nch) {
            int k0n = (ch + 1) * BKG;
#pragma unroll
            for (int it = 0; it < 4; it++) {
                areg[it] = *(const float4*)(Ap + (size_t)it * 32 * K + k0n);
                breg[it] = *(const float4*)(Wp + (size_t)it * 32 * K + k0n);
            }
        }
        const uint32_t* as = (const uint32_t*)(As + buf * BMG * SSTR + warp_m * 64 * SSTR);
        const uint32_t* bs = (const uint32_t*)(Bs + buf * BNG * SSTR + warp_n * 32 * SSTR);
#pragma unroll
        for (int ks = 0; ks < 4; ks++) {
            int k0 = ks * 8;
            uint32_t af[4][4], bf[4][2];
#pragma unroll
            for (int t = 0; t < 4; t++) {
                int row = t * 16 + gr;
                af[t][0] = as[row * SSTR + k0 + gc];
                af[t][1] = as[(row + 8) * SSTR + k0 + gc];
                af[t][2] = as[row * SSTR + k0 + gc + 4];
                af[t][3] = as[(row + 8) * SSTR + k0 + gc + 4];
            }
#pragma unroll
            for (int u = 0; u < 4; u++) {
                int col = u * 8 + gr;
                bf[u][0] = bs[col * SSTR + k0 + gc];
                bf[u][1] = bs[col * SSTR + k0 + gc + 4];
            }
#pragma unroll
            for (int t = 0; t < 4; t++)
#pragma unroll
                for (int u = 0; u < 4; u++)
                    mma_tf32(c[t][u], af[t], bf[u]);
        }
        __syncthreads();
        if (ch + 1 < nch) {
            int nbuf = (ch + 1) & 1;
#pragma unroll
            for (int it = 0; it < 4; it++) {
                float* da = As + nbuf * BMG * SSTR + (lrow + it * 32) * SSTR + lc4;
                float* db = Bs + nbuf * BNG * SSTR + (lrow + it * 32) * SSTR + lc4;
                ((uint32_t*)da)[0] = f2tf32(areg[it].x); ((uint32_t*)da)[1] = f2tf32(areg[it].y);
                ((uint32_t*)da)[2] = f2tf32(areg[it].z); ((uint32_t*)da)[3] = f2tf32(areg[it].w);
                ((uint32_t*)db)[0] = f2tf32(breg[it].x); ((uint32_t*)db)[1] = f2tf32(breg[it].y);
                ((uint32_t*)db)[2] = f2tf32(breg[it].z); ((uint32_t*)db)[3] = f2tf32(breg[it].w);
            }
            __syncthreads();
        }
    }

#pragma unroll
    for (int t = 0; t < 4; t++) {
        int row = bm + warp_m * 64 + t * 16 + gr;
#pragma unroll
        for (int u = 0; u < 4; u++) {
            int col = bn + warp_n * 32 + u * 8 + 2 * gc;
            float2 bb = *(const float2*)(bias + col);
            float2 o0, o1;
            o0.x = (c[t][u][0] + bb.x) * alpha;
            o0.y = (c[t][u][1] + bb.y) * alpha;
            o1.x = (c[t][u][2] + bb.x) * alpha;
            o1.y = (c[t][u][3] + bb.y) * alpha;
            *(float2*)(C + (size_t)row * N + col) = o0;
            *(float2*)(C + (size_t)(row + 8) * N + col) = o1;
        }
    }
}

__global__ __launch_bounds__(256)
void qkv_gemm_kernel(const float* q_in, const float* k_in, const float* v_in,
                     const float* Wq, const float* Wk, const float* Wv,
                     const float* bq, const float* bk, const float* bv,
                     float* qo, float* ko, float* vo,
                     int M, int N, int K, float scaling,
                     const float* __restrict__ temp_ptr) {
    extern __shared__ float smg[];
    int z = blockIdx.z;
    const float* A; const float* W; const float* bias; float* C; float alpha;
    if (z == 0)      { A = q_in; W = Wq; bias = bq; C = qo; alpha = scaling * (*temp_ptr); }
    else if (z == 1) { A = k_in; W = Wk; bias = bk; C = ko; alpha = 1.0f; }
    else             { A = v_in; W = Wv; bias = bv; C = vo; alpha = 1.0f; }
    gemm_core(A, W, bias, C, M, N, K, alpha, smg);
}

__global__ __launch_bounds__(256)
void oproj_gemm_kernel(const float* __restrict__ A, const float* __restrict__ W,
                       const float* __restrict__ bias, float* __restrict__ C,
                       int M, int N, int K) {
    extern __shared__ float smg[];
    gemm_core(A, W, bias, C, M, N, K, 1.0f, smg);
}

// ---------------- mma.sync flash attention ---------------------------------
// 8 warps x m16 rows; 64-col tiles; QK^T and PV on tensor cores (tf32).
// V split hi+lo tf32 for accuracy. Global cols = one synthetic gather tile.
#define AT_BM 128
#define AT_BN 64
#define KSTR 36                        // u32 stride, K/Vh/Vl tiles
#define PSTR 68                        // u32 stride, P staging
#define OFF_K  0
#define OFF_VH (64 * KSTR)
#define OFF_VL (2 * 64 * KSTR)
#define OFF_P  (3 * 64 * KSTR)
#define OFF_GJ (OFF_P + 128 * PSTR)
#define ATT_SMEM ((OFF_GJ + 64) * 4)   // 62720 bytes

__global__ __launch_bounds__(256)
void sparse_attn_kernel(int T, int S, int E, const int* __restrict__ Wptr) {
    extern __shared__ float smf[];
    uint32_t* smu = (uint32_t*)smf;
    int* smgj = (int*)(smu + OFF_GJ);

    int b = blockIdx.z, h = blockIdx.y;
    int i0 = blockIdx.x * AT_BM;
    int tid = threadIdx.x;
    int w = tid >> 5, lane = tid & 31;
    int gr = lane >> 2, gc = lane & 3;
    int r0 = i0 + w * 16 + gr;
    int r1 = r0 + 8;

    const float* qb = g_q + (size_t)(b * T) * E + h * HD;
    const float* kbase = g_k + (size_t)b * S * E + h * HD;
    const float* vbase = g_v + (size_t)b * S * E + h * HD;

    // Q fragments (m16 k32, tf32)
    uint32_t qf[4][4];
#pragma unroll
    for (int kc = 0; kc < 4; kc++) {
        qf[kc][0] = f2tf32(qb[(size_t)r0 * E + kc * 8 + gc]);
        qf[kc][1] = f2tf32(qb[(size_t)r1 * E + kc * 8 + gc]);
        qf[kc][2] = f2tf32(qb[(size_t)r0 * E + kc * 8 + gc + 4]);
        qf[kc][3] = f2tf32(qb[(size_t)r1 * E + kc * 8 + gc + 4]);
    }

    int Wl = *Wptr;
    int ov = Wl / 4, step = Wl - ov;

    int klo0 = (r0 >= Wl) ? (r0 - Wl) / step + 1 : 0;
    int khi0 = r0 / step;
    int rlo0 = max(0, klo0 * step - ov);
    int rhi0 = min(S, khi0 * step + Wl + ov);
    int klo1 = (r1 >= Wl) ? (r1 - Wl) / step + 1 : 0;
    int khi1 = r1 / step;
    int rlo1 = max(0, klo1 * step - ov);
    int rhi1 = min(S, khi1 * step + Wl + ov);

    int cklo = (i0 >= Wl) ? (i0 - Wl) / step + 1 : 0;
    int ckhi = (i0 + AT_BM - 1) / step;
    int c_lo = max(0, cklo * step - ov);
    int c_hi = min(S, ckhi * step + Wl + ov);

    float m0 = -1e30f, m1 = -1e30f, l0 = 0.f, l1 = 0.f;
    float o[4][4];
#pragma unroll
    for (int dn = 0; dn < 4; dn++)
#pragma unroll
        for (int e = 0; e < 4; e++) o[dn][e] = 0.f;

    int lrow = tid >> 2;            // 0..63 : tile col (seq) loaded by this thread
    int lpart = (tid & 3) * 8;      // dim part

    int prow0 = OFF_P + (w * 16 + gr) * PSTR;
    int prow1 = prow0 + 8 * PSTR;

    auto compute_tile = [&](int j0, bool gather, int ng) {
        // ---- QK^T: S fragments ----
        float c[8][4];
#pragma unroll
        for (int n = 0; n < 8; n++) {
            c[n][0] = 0.f; c[n][1] = 0.f; c[n][2] = 0.f; c[n][3] = 0.f;
#pragma unroll
            for (int kc = 0; kc < 4; kc++) {
                uint32_t bb[2];
                bb[0] = smu[OFF_K + (n * 8 + gr) * KSTR + kc * 8 + gc];
                bb[1] = smu[OFF_K + (n * 8 + gr) * KSTR + kc * 8 + gc + 4];
                mma_tf32(c[n], qf[kc], bb);
            }
        }
        // ---- masking ----
        bool fullmask = false;
        if (!gather) {
            bool f = (j0 >= rlo0) && (j0 + AT_BN <= rhi0) &&
                     (j0 >= rlo1) && (j0 + AT_BN <= rhi1);
            fullmask = __all_sync(0xffffffffu, f);
        }
        if (!fullmask) {
#pragma unroll
            for (int n = 0; n < 8; n++) {
                int e0 = n * 8 + 2 * gc, e1 = e0 + 1;
                bool v00, v01, v10, v11;
                if (!gather) {
                    int col0 = j0 + e0, col1 = j0 + e1;
                    v00 = (col0 >= rlo0) && (col0 < rhi0);
                    v01 = (col1 >= rlo0) && (col1 < rhi0);
                    v10 = (col0 >= rlo1) && (col0 < rhi1);
                    v11 = (col1 >= rlo1) && (col1 < rhi1);
                } else {
                    int gj0 = smgj[e0], gj1 = smgj[e1];
                    v00 = (e0 < ng) && ((gj0 < rlo0) || (gj0 >= rhi0));
                    v01 = (e1 < ng) && ((gj1 < rlo0) || (gj1 >= rhi0));
                    v10 = (e0 < ng) && ((gj0 < rlo1) || (gj0 >= rhi1));
                    v11 = (e1 < ng) && ((gj1 < rlo1) || (gj1 >= rhi1));
                }
                if (!v00) c[n][0] = -INFINITY;
                if (!v01) c[n][1] = -INFINITY;
                if (!v10) c[n][2] = -INFINITY;
                if (!v11) c[n][3] = -INFINITY;
            }
        }
        // ---- online softmax ----
        float cm0 = -INFINITY, cm1 = -INFINITY;
#pragma unroll
        for (int n = 0; n < 8; n++) {
            cm0 = fmaxf(cm0, fmaxf(c[n][0], c[n][1]));
            cm1 = fmaxf(cm1, fmaxf(c[n][2], c[n][3]));
        }
        cm0 = fmaxf(cm0, __shfl_xor_sync(0xffffffffu, cm0, 1));
        cm0 = fmaxf(cm0, __shfl_xor_sync(0xffffffffu, cm0, 2));
        cm1 = fmaxf(cm1, __shfl_xor_sync(0xffffffffu, cm1, 1));
        cm1 = fmaxf(cm1, __shfl_xor_sync(0xffffffffu, cm1, 2));
        float mn0 = fmaxf(m0, cm0), mn1 = fmaxf(m1, cm1);
        float sc0 = __expf(m0 - mn0), sc1 = __expf(m1 - mn1);
        m0 = mn0; m1 = mn1;
        l0 *= sc0; l1 *= sc1;
#pragma unroll
        for (int dn = 0; dn < 4; dn++) {
            o[dn][0] *= sc0; o[dn][1] *= sc0;
            o[dn][2] *= sc1; o[dn][3] *= sc1;
        }
        // ---- exp + stage P (tf32) ----
#pragma unroll
        for (int n = 0; n < 8; n++) {
            float p0 = __expf(c[n][0] - m0);
            float p1 = __expf(c[n][1] - m0);
            float p2 = __expf(c[n][2] - m1);
            float p3 = __expf(c[n][3] - m1);
            l0 += p0 + p1;
            l1 += p2 + p3;
            uint2 u0; u0.x = f2tf32(p0); u0.y = f2tf32(p1);
            *(uint2*)&smu[prow0 + n * 8 + 2 * gc] = u0;
            uint2 u1; u1.x = f2tf32(p2); u1.y = f2tf32(p3);
            *(uint2*)&smu[prow1 + n * 8 + 2 * gc] = u1;
        }
        __syncwarp();
        // ---- PV: O += P x (Vhi + Vlo) ----
#pragma unroll
        for (int k2 = 0; k2 < 8; k2++) {
            uint32_t a[4];
            a[0] = smu[prow0 + k2 * 8 + gc];
            a[1] = smu[prow1 + k2 * 8 + gc];
            a[2] = smu[prow0 + k2 * 8 + gc + 4];
            a[3] = smu[prow1 + k2 * 8 + gc + 4];
#pragma unroll
            for (int dn = 0; dn < 4; dn++) {
                uint32_t bh[2], bl[2];
                bh[0] = smu[OFF_VH + (k2 * 8 + gc) * KSTR + dn * 8 + gr];
                bh[1] = smu[OFF_VH + (k2 * 8 + gc + 4) * KSTR + dn * 8 + gr];
                mma_tf32(o[dn], a, bh);
                bl[0] = smu[OFF_VL + (k2 * 8 + gc) * KSTR + dn * 8 + gr];
                bl[1] = smu[OFF_VL + (k2 * 8 + gc + 4) * KSTR + dn * 8 + gr];
                mma_tf32(o[dn], a, bl);
            }
        }
    };

    // ---- main tiles over the CTA's contiguous range ----
    for (int j0 = (c_lo & ~(AT_BN - 1)); j0 < c_hi; j0 += AT_BN) {
        const float* kp = kbase + (size_t)(j0 + lrow) * E + lpart;
        const float* vp = vbase + (size_t)(j0 + lrow) * E + lpart;
#pragma unroll
        for (int c4 = 0; c4 < 8; c4 += 4) {
            float4 kv = *(const float4*)(kp + c4);
            uint4 kt;
            kt.x = f2tf32(kv.x); kt.y = f2tf32(kv.y);
            kt.z = f2tf32(kv.z); kt.w = f2tf32(kv.w);
            *(uint4*)&smu[OFF_K + lrow * KSTR + lpart + c4] = kt;
            float4 vv = *(const float4*)(vp + c4);
            uint4 vh;
            vh.x = f2tf32(vv.x); vh.y = f2tf32(vv.y);
            vh.z = f2tf32(vv.z); vh.w = f2tf32(vv.w);
            uint4 vl;
            vl.x = f2tf32(vv.x - __uint_as_float(vh.x));
            vl.y = f2tf32(vv.y - __uint_as_float(vh.y));
            vl.z = f2tf32(vv.z - __uint_as_float(vh.z));
            vl.w = f2tf32(vv.w - __uint_as_float(vh.w));
            *(uint4*)&smu[OFF_VH + lrow * KSTR + lpart + c4] = vh;
            *(uint4*)&smu[OFF_VL + lrow * KSTR + lpart + c4] = vl;
        }
        __syncthreads();
        compute_tile(j0, false, 0);
        __syncthreads();
    }

    // ---- gather tile: global columns ----
    int ng = g_gcount;
    if (ng > 0) {
        if (tid < 64) smgj[tid] = (tid < ng) ? g_gcols[tid] : 0x7fffffff;
        if (lrow < ng) {
            int j = g_gcols[lrow];
            const float* kp = kbase + (size_t)j * E + lpart;
            const float* vp = vbase + (size_t)j * E + lpart;
#pragma unroll
            for (int c4 = 0; c4 < 8; c4 += 4) {
                float4 kv = *(const float4*)(kp + c4);
                uint4 kt;
                kt.x = f2tf32(kv.x); kt.y = f2tf32(kv.y);
                kt.z = f2tf32(kv.z); kt.w = f2tf32(kv.w);
                *(uint4*)&smu[OFF_K + lrow * KSTR + lpart + c4] = kt;
                float4 vv = *(const float4*)(vp + c4);
                uint4 vh;
                vh.x = f2tf32(vv.x); vh.y = f2tf32(vv.y);
                vh.z = f2tf32(vv.z); vh.w = f2tf32(vv.w);
                uint4 vl;
                vl.x = f2tf32(vv.x - __uint_as_float(vh.x));
                vl.y = f2tf32(vv.y - __uint_as_float(vh.y));
                vl.z = f2tf32(vv.z - __uint_as_float(vh.z));
                vl.w = f2tf32(vv.w - __uint_as_float(vh.w));
                *(uint4*)&smu[OFF_VH + lrow * KSTR + lpart + c4] = vh;
                *(uint4*)&smu[OFF_VL + lrow * KSTR + lpart + c4] = vl;
            }
        }
        __syncthreads();
        compute_tile(0, true, ng);
    }

    // ---- finalize ----
    l0 += __shfl_xor_sync(0xffffffffu, l0, 1);
    l0 += __shfl_xor_sync(0xffffffffu, l0, 2);
    l1 += __shfl_xor_sync(0xffffffffu, l1, 1);
    l1 += __shfl_xor_sync(0xffffffffu, l1, 2);
    float inv0 = 1.0f / l0, inv1 = 1.0f / l1;

    float* o0p = g_ao + ((size_t)(b * T) + r0) * E + h * HD;
    float* o1p = g_ao + ((size_t)(b * T) + r1) * E + h * HD;
#pragma unroll
    for (int dn = 0; dn < 4; dn++) {
        float2 w0; w0.x = o[dn][0] * inv0; w0.y = o[dn][1] * inv0;
        float2 w1; w1.x = o[dn][2] * inv1; w1.y = o[dn][3] * inv1;
        *(float2*)(o0p + dn * 8 + 2 * gc) = w0;
        *(float2*)(o1p + dn * 8 + 2 * gc) = w1;
    }
}

// ---------------- launch -----------------------------------------------------
extern "C" void kernel_launch(void* const* d_in, const int* in_sizes, int n_in,
                              void* d_out, int out_size) {
    const float* query = (const float*)d_in[0];
    const float* key_  = (const float*)d_in[1];
    const float* value = (const float*)d_in[2];
    const float* Wq = (const float*)d_in[3];
    const float* bq = (const float*)d_in[4];
    const float* Wk = (const float*)d_in[5];
    const float* bk = (const float*)d_in[6];
    const float* Wv = (const float*)d_in[7];
    const float* bv = (const float*)d_in[8];
    const float* Wo = (const float*)d_in[9];
    const float* bo = (const float*)d_in[10];
    const float* temperature = (const float*)d_in[11];
    const int* wsize = (const int*)d_in[12];
    const int* gnum  = (const int*)d_in[13];
    float* out = (float*)d_out;

    int E = in_sizes[4];                 // 512
    int B = B_CONST;
    int T = in_sizes[0] / (B * E);       // 2048
    int S = in_sizes[1] / (B * E);       // 2048
    int M = B * T;                       // 4096
    int hd = E / H_NUM;

    float *qb, *kb, *vb, *aob;
    cudaGetSymbolAddress((void**)&qb,  g_q);
    cudaGetSymbolAddress((void**)&kb,  g_k);
    cudaGetSymbolAddress((void**)&vb,  g_v);
    cudaGetSymbolAddress((void**)&aob, g_ao);

    glist_kernel<<<1, 32>>>(S, gnum);

    cudaFuncSetAttribute(qkv_gemm_kernel,
                         cudaFuncAttributeMaxDynamicSharedMemorySize, GEMM_SMEM);
    cudaFuncSetAttribute(oproj_gemm_kernel,
                         cudaFuncAttributeMaxDynamicSharedMemorySize, GEMM_SMEM);

    float scaling = 1.0f / sqrtf((float)hd);
    dim3 qkv_grid(E / BNG, M / BMG, 3);          // (4, 32, 3)
    qkv_gemm_kernel<<<qkv_grid, 256, GEMM_SMEM>>>(
        query, key_, value, Wq, Wk, Wv, bq, bk, bv,
        qb, kb, vb, M, E, E, scaling, temperature);

    cudaFuncSetAttribute(sparse_attn_kernel,
                         cudaFuncAttributeMaxDynamicSharedMemorySize, ATT_SMEM);
    sparse_attn_kernel<<<dim3(T / AT_BM, H_NUM, B), 256, ATT_SMEM>>>(T, S, E, wsize);

    dim3 ogrid(E / BNG, M / BMG);                // (4, 32)
    oproj_gemm_kernel<<<ogrid, 256, GEMM_SMEM>>>(aob, Wo, bo, out, M, E, E);
}